// round 4
// baseline (speedup 1.0000x reference)
#include <cuda_runtime.h>
#include <cuda_fp16.h>
#include <cstdint>

#define N_NODES 50000
#define N_EDGES 600000
#define D 128

// ---------------- scratch (static device globals; no allocation) ----------
__device__ float  g_dis[N_NODES];                // deg^{-1/2}
__device__ int    g_counts[N_NODES];             // in-degree histogram
__device__ int    g_base[N_NODES];               // CSR chunk base (unordered)
__device__ int    g_cursor[N_NODES];             // scatter cursors
__device__ int    g_total;                       // running total for base alloc
__device__ int    g_csr_src[N_EDGES];            // src per CSR slot
__device__ __half g_hw[(size_t)N_NODES * D];     // hw' buffer (dis-scaled, fp16)
__device__ float  g_act[(size_t)N_NODES * D];    // activation buffer (fp32)
__device__ float  g_hw3[N_NODES];                // layer-3 GEMV result (dis-scaled)

// ---------------- preprocessing ------------------------------------------
__global__ void hist_kernel(const int* __restrict__ dst) {
    int i = blockIdx.x * blockDim.x + threadIdx.x;   // handles 4 edges
    if (i * 4 < N_EDGES) {
        int4 d4 = *(const int4*)(dst + i * 4);
        atomicAdd(&g_counts[d4.x], 1);
        atomicAdd(&g_counts[d4.y], 1);
        atomicAdd(&g_counts[d4.z], 1);
        atomicAdd(&g_counts[d4.w], 1);
    }
}

__global__ void prefix_kernel() {
    __shared__ int sh[256];
    __shared__ int block_base;
    int i = blockIdx.x * 256 + threadIdx.x;
    int c = (i < N_NODES) ? g_counts[i] : 0;
    int v = c;
    sh[threadIdx.x] = v;
    __syncthreads();
    #pragma unroll
    for (int off = 1; off < 256; off <<= 1) {
        int t = (threadIdx.x >= off) ? sh[threadIdx.x - off] : 0;
        __syncthreads();
        v += t;
        sh[threadIdx.x] = v;
        __syncthreads();
    }
    if (threadIdx.x == 255) block_base = atomicAdd(&g_total, v);
    __syncthreads();
    if (i < N_NODES) {
        int base = block_base + v - c;
        g_base[i]   = base;
        g_cursor[i] = base;
        g_dis[i]    = rsqrtf((float)c + 1.0f);
    }
}

__global__ void scatter_kernel(const int* __restrict__ src,
                               const int* __restrict__ dst) {
    int i = blockIdx.x * blockDim.x + threadIdx.x;
    if (i * 4 < N_EDGES) {
        int4 s4 = *(const int4*)(src + i * 4);
        int4 d4 = *(const int4*)(dst + i * 4);
        int p0 = atomicAdd(&g_cursor[d4.x], 1);
        int p1 = atomicAdd(&g_cursor[d4.y], 1);
        int p2 = atomicAdd(&g_cursor[d4.z], 1);
        int p3 = atomicAdd(&g_cursor[d4.w], 1);
        g_csr_src[p0] = s4.x;
        g_csr_src[p1] = s4.y;
        g_csr_src[p2] = s4.z;
        g_csr_src[p3] = s4.w;
    }
}

// ---------------- 3xTF32 tensor-core GEMM (fragment-major smem, 2-stage) --
// OUT(fp16)[r][c] = (X[M,128] @ W[128,128])[r][c] * g_dis[r]
// block tile 128(M) x 64(N), kc chunk 16 (two k8 groups), 8 warps 4x2,
// warp tile 32x32: acc[2][4] of m16n8.

__device__ __forceinline__ uint32_t f2tf32(float x) {
    uint32_t r;
    asm("cvt.rna.tf32.f32 %0, %1;" : "=r"(r) : "f"(x));
    return r;
}
__device__ __forceinline__ void split_tf32(float x, uint32_t& hi, uint32_t& lo) {
    hi = f2tf32(x);
    float l = x - __uint_as_float(hi);
    lo = f2tf32(l);
}
__device__ __forceinline__ void mma_tf32(float4& d, const uint32_t* a, const uint32_t* b) {
    asm volatile(
        "mma.sync.aligned.m16n8k8.row.col.f32.tf32.tf32.f32 "
        "{%0,%1,%2,%3}, {%4,%5,%6,%7}, {%8,%9}, {%0,%1,%2,%3};"
        : "+f"(d.x), "+f"(d.y), "+f"(d.z), "+f"(d.w)
        : "r"(a[0]), "r"(a[1]), "r"(a[2]), "r"(a[3]), "r"(b[0]), "r"(b[1]));
}

// smem sizes (floats): A per stage: 8 mtiles * 2 k8 * 32 lanes * 4 regs = 2048
//                      B per stage: 8 ntiles * 2 k8 * 32 lanes * 2 regs = 1024
#define A_STAGE 2048
#define B_STAGE 1024

// store one row-chunk float4 of A (row r, cols c4..c4+3 of the 16-col chunk)
// into fragment-major layout: [mt][k8][lane][reg], value (r,c)->
//   lane=(r&7)*4+(c&3), reg=((r&15)>=8) + 2*((c&7)>=4)
__device__ __forceinline__ void stage_A(float4 v, int r, int c4, int st,
                                        float* sAh, float* sAl) {
    int mt = r >> 4;
    int k8 = c4 >> 3;
    int reg = (((r & 15) >= 8) ? 1 : 0) + ((c4 & 4) ? 2 : 0);
    int base = (((st * 8 + mt) * 2 + k8) * 32 + (r & 7) * 4) * 4 + reg;
    uint32_t h, l;
    split_tf32(v.x, h, l); sAh[base + 0]  = __uint_as_float(h); sAl[base + 0]  = __uint_as_float(l);
    split_tf32(v.y, h, l); sAh[base + 4]  = __uint_as_float(h); sAl[base + 4]  = __uint_as_float(l);
    split_tf32(v.z, h, l); sAh[base + 8]  = __uint_as_float(h); sAl[base + 8]  = __uint_as_float(l);
    split_tf32(v.w, h, l); sAh[base + 12] = __uint_as_float(h); sAl[base + 12] = __uint_as_float(l);
}

// store one k-row float4 of W chunk (k row r of 16, local cols c4..c4+3 of 64)
// layout: [nt][k8][lane][reg], value (n,k)-> lane=(n&7)*4+(k&3), reg=((k&7)>=4)
__device__ __forceinline__ void stage_B(float4 v, int r, int c4, int st,
                                        float* sBh, float* sBl) {
    int k8 = r >> 3;
    int t  = r & 3;
    int reg = ((r & 7) >= 4) ? 1 : 0;
    int nt = c4 >> 3;
    int base = (((st * 8 + nt) * 2 + k8) * 32 + (c4 & 7) * 4 + t) * 2 + reg;
    uint32_t h, l;
    split_tf32(v.x, h, l); sBh[base + 0]  = __uint_as_float(h); sBl[base + 0]  = __uint_as_float(l);
    split_tf32(v.y, h, l); sBh[base + 8]  = __uint_as_float(h); sBl[base + 8]  = __uint_as_float(l);
    split_tf32(v.z, h, l); sBh[base + 16] = __uint_as_float(h); sBl[base + 16] = __uint_as_float(l);
    split_tf32(v.w, h, l); sBh[base + 24] = __uint_as_float(h); sBl[base + 24] = __uint_as_float(l);
}

__global__ __launch_bounds__(256, 2)
void gemm_tf32_kernel(const float* __restrict__ X, const float* __restrict__ W,
                      __half* __restrict__ OUT, int M) {
    __shared__ float sAh[2 * A_STAGE];
    __shared__ float sAl[2 * A_STAGE];
    __shared__ float sBh[2 * B_STAGE];
    __shared__ float sBl[2 * B_STAGE];

    int tid = threadIdx.x;
    int wid = tid >> 5, lane = tid & 31;
    int wm = wid >> 1, wn = wid & 1;         // 4 x 2 warp grid
    int g = lane >> 2, t = lane & 3;
    int block_row = blockIdx.x * 128;
    int n0 = blockIdx.y * 64;

    // per-thread load coordinates
    int a_r0 = tid >> 2;                 // rows r0 and r0+64
    int a_c4 = (tid & 3) * 4;            // col within 16-chunk
    int b_r  = tid >> 4;                 // k row within 16-chunk
    int b_c4 = (tid & 15) * 4;           // local n col

    float4 acc[2][4];
    #pragma unroll
    for (int mt = 0; mt < 2; mt++)
        #pragma unroll
        for (int nt = 0; nt < 4; nt++)
            acc[mt][nt] = make_float4(0.f, 0.f, 0.f, 0.f);

    // prologue: fill stage 0
    {
        int gr0 = block_row + a_r0, gr1 = gr0 + 64;
        float4 vA0 = (gr0 < M) ? *(const float4*)(X + (size_t)gr0 * D + a_c4)
                               : make_float4(0.f, 0.f, 0.f, 0.f);
        float4 vA1 = (gr1 < M) ? *(const float4*)(X + (size_t)gr1 * D + a_c4)
                               : make_float4(0.f, 0.f, 0.f, 0.f);
        float4 vB  = *(const float4*)(W + (size_t)b_r * D + n0 + b_c4);
        stage_A(vA0, a_r0,      a_c4, 0, sAh, sAl);
        stage_A(vA1, a_r0 + 64, a_c4, 0, sAh, sAl);
        stage_B(vB,  b_r,       b_c4, 0, sBh, sBl);
    }
    __syncthreads();

    #pragma unroll
    for (int it = 0; it < 8; it++) {
        const int cur = it & 1, nxt = cur ^ 1;
        float4 vA0, vA1, vB;
        if (it < 7) {
            int kc = (it + 1) * 16;
            int gr0 = block_row + a_r0, gr1 = gr0 + 64;
            vA0 = (gr0 < M) ? *(const float4*)(X + (size_t)gr0 * D + kc + a_c4)
                            : make_float4(0.f, 0.f, 0.f, 0.f);
            vA1 = (gr1 < M) ? *(const float4*)(X + (size_t)gr1 * D + kc + a_c4)
                            : make_float4(0.f, 0.f, 0.f, 0.f);
            vB  = *(const float4*)(W + (size_t)(kc + b_r) * D + n0 + b_c4);
        }

        // compute from stage cur
        #pragma unroll
        for (int k8 = 0; k8 < 2; k8++) {
            uint4 ah[2], al[2];
            #pragma unroll
            for (int mt = 0; mt < 2; mt++) {
                int idx = (((cur * 8 + (wm * 2 + mt)) * 2 + k8) * 32 + lane) * 4;
                ah[mt] = *(const uint4*)&sAh[idx];
                al[mt] = *(const uint4*)&sAl[idx];
            }
            uint2 bh[4], bl[4];
            #pragma unroll
            for (int nt = 0; nt < 4; nt++) {
                int idx = (((cur * 8 + (wn * 4 + nt)) * 2 + k8) * 32 + lane) * 2;
                bh[nt] = *(const uint2*)&sBh[idx];
                bl[nt] = *(const uint2*)&sBl[idx];
            }
            #pragma unroll
            for (int mt = 0; mt < 2; mt++)
                #pragma unroll
                for (int nt = 0; nt < 4; nt++) {
                    mma_tf32(acc[mt][nt], (const uint32_t*)&ah[mt], (const uint32_t*)&bh[nt]);
                    mma_tf32(acc[mt][nt], (const uint32_t*)&ah[mt], (const uint32_t*)&bl[nt]);
                    mma_tf32(acc[mt][nt], (const uint32_t*)&al[mt], (const uint32_t*)&bh[nt]);
                }
        }

        if (it < 7) {
            stage_A(vA0, a_r0,      a_c4, nxt, sAh, sAl);
            stage_A(vA1, a_r0 + 64, a_c4, nxt, sAh, sAl);
            stage_B(vB,  b_r,       b_c4, nxt, sBh, sBl);
        }
        __syncthreads();
    }

    // epilogue: scale rows by dis, store fp16
    #pragma unroll
    for (int mt = 0; mt < 2; mt++) {
        int r0 = block_row + wm * 32 + mt * 16 + g;
        int r1 = r0 + 8;
        float d0 = (r0 < M) ? g_dis[r0] : 0.f;
        float d1 = (r1 < M) ? g_dis[r1] : 0.f;
        #pragma unroll
        for (int nt = 0; nt < 4; nt++) {
            int col = n0 + wn * 32 + nt * 8 + 2 * t;
            float4 c = acc[mt][nt];
            if (r0 < M)
                *(__half2*)(OUT + (size_t)r0 * D + col) = __floats2half2_rn(c.x * d0, c.y * d0);
            if (r1 < M)
                *(__half2*)(OUT + (size_t)r1 * D + col) = __floats2half2_rn(c.z * d1, c.w * d1);
        }
    }
}

// ---------------- aggregation (warp per node), F=128, fp16 gathers --------
template <bool FUSE_GEMV>
__global__ __launch_bounds__(256)
void agg128_kernel(const __half* __restrict__ HW, const float* __restrict__ bias,
                   float* __restrict__ OUT, const float* __restrict__ W3) {
    int warp = (blockIdx.x * blockDim.x + threadIdx.x) >> 5;
    int lane = threadIdx.x & 31;
    if (warp >= N_NODES) return;
    int node = warp;

    const uint2* rowp = (const uint2*)(HW + (size_t)node * D) + lane;
    uint2 sv = *rowp;
    float2 a0 = __half22float2(*(const __half2*)&sv.x);
    float2 a1 = __half22float2(*(const __half2*)&sv.y);
    float4 acc = make_float4(a0.x, a0.y, a1.x, a1.y);

    int beg = g_base[node];
    int end = beg + g_counts[node];
    int e = beg;
    for (; e + 2 <= end; e += 2) {
        int s0 = __ldg(&g_csr_src[e]);
        int s1 = __ldg(&g_csr_src[e + 1]);
        uint2 v0 = *((const uint2*)(HW + (size_t)s0 * D) + lane);
        uint2 v1 = *((const uint2*)(HW + (size_t)s1 * D) + lane);
        float2 f00 = __half22float2(*(const __half2*)&v0.x);
        float2 f01 = __half22float2(*(const __half2*)&v0.y);
        float2 f10 = __half22float2(*(const __half2*)&v1.x);
        float2 f11 = __half22float2(*(const __half2*)&v1.y);
        acc.x += f00.x + f10.x; acc.y += f00.y + f10.y;
        acc.z += f01.x + f11.x; acc.w += f01.y + f11.y;
    }
    if (e < end) {
        int s = __ldg(&g_csr_src[e]);
        uint2 v = *((const uint2*)(HW + (size_t)s * D) + lane);
        float2 f0 = __half22float2(*(const __half2*)&v.x);
        float2 f1 = __half22float2(*(const __half2*)&v.y);
        acc.x += f0.x; acc.y += f0.y; acc.z += f1.x; acc.w += f1.y;
    }

    float dn = g_dis[node];
    float4 b = ((const float4*)bias)[lane];
    acc.x = fmaxf(acc.x * dn + b.x, 0.f);
    acc.y = fmaxf(acc.y * dn + b.y, 0.f);
    acc.z = fmaxf(acc.z * dn + b.z, 0.f);
    acc.w = fmaxf(acc.w * dn + b.w, 0.f);

    if (FUSE_GEMV) {
        float4 w = ((const float4*)W3)[lane];
        float dot = acc.x * w.x + acc.y * w.y + acc.z * w.z + acc.w * w.w;
        #pragma unroll
        for (int off = 16; off > 0; off >>= 1)
            dot += __shfl_down_sync(0xFFFFFFFFu, dot, off);
        if (lane == 0) g_hw3[node] = dot * dn;
    } else {
        ((float4*)(OUT + (size_t)node * D))[lane] = acc;
    }
}

// ---------------- layer 3: scalar aggregation -----------------------------
__global__ void agg3_kernel(const float* __restrict__ b3, float* __restrict__ OUT) {
    int node = blockIdx.x * blockDim.x + threadIdx.x;
    if (node >= N_NODES) return;
    float acc = g_hw3[node];
    int beg = g_base[node];
    int end = beg + g_counts[node];
    for (int e = beg; e < end; e++)
        acc += g_hw3[__ldg(&g_csr_src[e])];
    OUT[node] = fmaxf(acc * g_dis[node] + b3[0], 0.f);
}

// ---------------- launch ---------------------------------------------------
extern "C" void kernel_launch(void* const* d_in, const int* in_sizes, int n_in,
                              void* d_out, int out_size) {
    const float* x  = (const float*)d_in[0];
    const int*   ei = (const int*)d_in[1];
    const float* W1 = (const float*)d_in[2];
    const float* b1 = (const float*)d_in[3];
    const float* W2 = (const float*)d_in[4];
    const float* b2 = (const float*)d_in[5];
    const float* W3 = (const float*)d_in[6];
    const float* b3 = (const float*)d_in[7];
    float* out = (float*)d_out;

    const int* src = ei;
    const int* dst = ei + N_EDGES;

    __half* hw;  cudaGetSymbolAddress((void**)&hw,  g_hw);
    float*  act; cudaGetSymbolAddress((void**)&act, g_act);
    int* counts; cudaGetSymbolAddress((void**)&counts, g_counts);
    int* total;  cudaGetSymbolAddress((void**)&total,  g_total);

    int nb_nodes = (N_NODES + 255) / 256;
    int nb_edge4 = (N_EDGES / 4 + 255) / 256;
    int nb_warp  = (N_NODES * 32 + 255) / 256;
    dim3 gemm_grid((N_NODES + 127) / 128, 2);

    // preprocessing: unordered CSR by dst
    cudaMemsetAsync(counts, 0, N_NODES * sizeof(int));
    cudaMemsetAsync(total, 0, sizeof(int));
    hist_kernel<<<nb_edge4, 256>>>(dst);
    prefix_kernel<<<nb_nodes, 256>>>();
    scatter_kernel<<<nb_edge4, 256>>>(src, dst);

    // layer 1
    gemm_tf32_kernel<<<gemm_grid, 256>>>(x, W1, hw, N_NODES);
    agg128_kernel<false><<<nb_warp, 256>>>(hw, b1, act, nullptr);
    // layer 2 (+ fused layer-3 GEMV)
    gemm_tf32_kernel<<<gemm_grid, 256>>>(act, W2, hw, N_NODES);
    agg128_kernel<true><<<nb_warp, 256>>>(hw, b2, nullptr, W3);
    // layer 3 aggregation
    agg3_kernel<<<nb_nodes, 256>>>(b3, out);
}

// round 5
// speedup vs baseline: 1.8649x; 1.8649x over previous
#include <cuda_runtime.h>
#include <cuda_fp16.h>
#include <cstdint>

#define N_NODES 50000
#define N_EDGES 600000
#define D 128

// ---------------- scratch (static device globals; no allocation) ----------
__device__ float  g_dis[N_NODES];                // deg^{-1/2}
__device__ int    g_counts[N_NODES];             // in-degree histogram
__device__ int    g_base[N_NODES];               // CSR chunk base (unordered)
__device__ int    g_cursor[N_NODES];             // scatter cursors
__device__ int    g_total;                       // running total for base alloc
__device__ int    g_csr_src[N_EDGES];            // src per CSR slot
__device__ __half g_hw[(size_t)N_NODES * D];     // hw' buffer (dis-scaled, fp16)
__device__ float  g_act[(size_t)N_NODES * D];    // activation buffer (fp32)
__device__ float  g_hw3[N_NODES];                // layer-3 GEMV result (dis-scaled)

// ---------------- preprocessing ------------------------------------------
__global__ void hist_kernel(const int* __restrict__ dst) {
    int i = blockIdx.x * blockDim.x + threadIdx.x;   // handles 4 edges
    if (i * 4 < N_EDGES) {
        int4 d4 = *(const int4*)(dst + i * 4);
        atomicAdd(&g_counts[d4.x], 1);
        atomicAdd(&g_counts[d4.y], 1);
        atomicAdd(&g_counts[d4.z], 1);
        atomicAdd(&g_counts[d4.w], 1);
    }
}

__global__ void prefix_kernel() {
    __shared__ int sh[256];
    __shared__ int block_base;
    int i = blockIdx.x * 256 + threadIdx.x;
    int c = (i < N_NODES) ? g_counts[i] : 0;
    int v = c;
    sh[threadIdx.x] = v;
    __syncthreads();
    #pragma unroll
    for (int off = 1; off < 256; off <<= 1) {
        int t = (threadIdx.x >= off) ? sh[threadIdx.x - off] : 0;
        __syncthreads();
        v += t;
        sh[threadIdx.x] = v;
        __syncthreads();
    }
    if (threadIdx.x == 255) block_base = atomicAdd(&g_total, v);
    __syncthreads();
    if (i < N_NODES) {
        int base = block_base + v - c;
        g_base[i]   = base;
        g_cursor[i] = base;
        g_dis[i]    = rsqrtf((float)c + 1.0f);
    }
}

__global__ void scatter_kernel(const int* __restrict__ src,
                               const int* __restrict__ dst) {
    int i = blockIdx.x * blockDim.x + threadIdx.x;
    if (i * 4 < N_EDGES) {
        int4 s4 = *(const int4*)(src + i * 4);
        int4 d4 = *(const int4*)(dst + i * 4);
        int p0 = atomicAdd(&g_cursor[d4.x], 1);
        int p1 = atomicAdd(&g_cursor[d4.y], 1);
        int p2 = atomicAdd(&g_cursor[d4.z], 1);
        int p3 = atomicAdd(&g_cursor[d4.w], 1);
        g_csr_src[p0] = s4.x;
        g_csr_src[p1] = s4.y;
        g_csr_src[p2] = s4.z;
        g_csr_src[p3] = s4.w;
    }
}

// ---------------- fp16 hi/lo 3-term tensor-core GEMM with ldmatrix -------
// OUT(fp16)[r][c] = (X[M,128] @ W[128,128])[r][c] * g_dis[r]
// block tile 128(M) x 64(N); kc chunk 16; 8 warps 4x2; warp tile 32x32.
// X,W split into fp16 hi/lo; D = hi*hi + hi*lo + lo*hi (error ~2^-22).

__device__ __forceinline__ void split2(float x, float y, uint32_t& hi, uint32_t& lo) {
    __half2 h = __floats2half2_rn(x, y);
    float2 hf = __half22float2(h);
    __half2 l = __floats2half2_rn(x - hf.x, y - hf.y);
    hi = *(uint32_t*)&h;
    lo = *(uint32_t*)&l;
}

__device__ __forceinline__ void ldsm_x4(uint32_t& r0, uint32_t& r1, uint32_t& r2,
                                        uint32_t& r3, uint32_t addr) {
    asm volatile("ldmatrix.sync.aligned.m8n8.x4.shared.b16 {%0,%1,%2,%3}, [%4];"
                 : "=r"(r0), "=r"(r1), "=r"(r2), "=r"(r3) : "r"(addr));
}

__device__ __forceinline__ void mma_f16(float4& d, const uint32_t* a, const uint32_t* b) {
    asm volatile(
        "mma.sync.aligned.m16n8k16.row.col.f32.f16.f16.f32 "
        "{%0,%1,%2,%3}, {%4,%5,%6,%7}, {%8,%9}, {%0,%1,%2,%3};"
        : "+f"(d.x), "+f"(d.y), "+f"(d.z), "+f"(d.w)
        : "r"(a[0]), "r"(a[1]), "r"(a[2]), "r"(a[3]), "r"(b[0]), "r"(b[1]));
}

// smem rows are 24 halves (48B) pitch: ldmatrix row offsets r*48 mod 128
// cover all 32 banks -> conflict-free LDSM.
#define APITCH 24
// sA: hi rows 0..127, lo rows 128..255 (each row = 16 halves used of 24)
// sB: hi rows 0..63 (n-major, k cols), lo rows 64..127

__global__ __launch_bounds__(256, 2)
void gemm_f16_kernel(const float* __restrict__ X, const float* __restrict__ W,
                     __half* __restrict__ OUT, int M) {
    __shared__ __align__(16) __half sA[256 * APITCH];
    __shared__ __align__(16) __half sB[128 * APITCH];

    int tid = threadIdx.x;
    int wid = tid >> 5, lane = tid & 31;
    int wm = wid >> 1, wn = wid & 1;         // 4 x 2 warp grid
    int g = lane >> 2, t = lane & 3;
    int block_row = blockIdx.x * 128;
    int n0 = blockIdx.y * 64;

    uint32_t sA_u = (uint32_t)__cvta_generic_to_shared(sA);
    uint32_t sB_u = (uint32_t)__cvta_generic_to_shared(sB);

    // load coordinates
    int a_r0 = tid >> 2;                 // rows a_r0 and a_r0+64
    int a_c4 = (tid & 3) * 4;            // col (floats) within 16-chunk
    int b_n  = tid & 63;                 // n col within 64
    int b_k0 = (tid >> 6) * 4;           // k row group within 16-chunk

    int gr0 = block_row + a_r0, gr1 = gr0 + 64;
    const float* Xp0 = X + (size_t)gr0 * D + a_c4;
    const float* Xp1 = X + (size_t)gr1 * D + a_c4;
    const float* Wp  = W + (size_t)b_k0 * D + n0 + b_n;

    // smem store addresses (bytes)
    uint32_t a_st0 = sA_u + a_r0 * 48 + a_c4 * 2;
    uint32_t a_st1 = sA_u + (a_r0 + 64) * 48 + a_c4 * 2;
    uint32_t b_st  = sB_u + b_n * 48 + b_k0 * 2;
    const uint32_t A_LO = 128 * 48;   // bytes
    const uint32_t B_LO = 64 * 48;

    // ldmatrix addresses (per-lane)
    uint32_t a_ld, b_ld;
    {
        int arow = wm * 32 + (lane & 7) + ((lane >> 3) & 1) * 8;
        int abyte = ((lane >> 4) & 1) * 16;
        a_ld = sA_u + arow * 48 + abyte;
        int m = lane >> 3;
        int nrow = wn * 32 + (m >> 1) * 8 + (lane & 7);
        int kb = (m & 1) * 16;
        b_ld = sB_u + nrow * 48 + kb;
    }

    float4 acc[2][4];
    #pragma unroll
    for (int mt = 0; mt < 2; mt++)
        #pragma unroll
        for (int nt = 0; nt < 4; nt++)
            acc[mt][nt] = make_float4(0.f, 0.f, 0.f, 0.f);

    // prologue: load chunk 0
    float4 vA0 = (gr0 < M) ? *(const float4*)Xp0 : make_float4(0.f, 0.f, 0.f, 0.f);
    float4 vA1 = (gr1 < M) ? *(const float4*)Xp1 : make_float4(0.f, 0.f, 0.f, 0.f);
    float  w0 = Wp[0], w1 = Wp[D], w2 = Wp[2 * D], w3 = Wp[3 * D];

    #pragma unroll
    for (int it = 0; it < 8; it++) {
        // stage current chunk into smem (convert + split)
        {
            uint32_t h01, l01, h23, l23;
            split2(vA0.x, vA0.y, h01, l01);
            split2(vA0.z, vA0.w, h23, l23);
            asm volatile("st.shared.v2.b32 [%0], {%1,%2};" :: "r"(a_st0), "r"(h01), "r"(h23));
            asm volatile("st.shared.v2.b32 [%0], {%1,%2};" :: "r"(a_st0 + A_LO), "r"(l01), "r"(l23));
            split2(vA1.x, vA1.y, h01, l01);
            split2(vA1.z, vA1.w, h23, l23);
            asm volatile("st.shared.v2.b32 [%0], {%1,%2};" :: "r"(a_st1), "r"(h01), "r"(h23));
            asm volatile("st.shared.v2.b32 [%0], {%1,%2};" :: "r"(a_st1 + A_LO), "r"(l01), "r"(l23));
            split2(w0, w1, h01, l01);
            split2(w2, w3, h23, l23);
            asm volatile("st.shared.v2.b32 [%0], {%1,%2};" :: "r"(b_st), "r"(h01), "r"(h23));
            asm volatile("st.shared.v2.b32 [%0], {%1,%2};" :: "r"(b_st + B_LO), "r"(l01), "r"(l23));
        }
        __syncthreads();

        // prefetch next chunk (global loads overlap the MMA block below)
        if (it < 7) {
            int kc = (it + 1) * 16;
            vA0 = (gr0 < M) ? *(const float4*)(Xp0 + kc) : make_float4(0.f, 0.f, 0.f, 0.f);
            vA1 = (gr1 < M) ? *(const float4*)(Xp1 + kc) : make_float4(0.f, 0.f, 0.f, 0.f);
            const float* wp = Wp + (size_t)kc * D;
            w0 = wp[0]; w1 = wp[D]; w2 = wp[2 * D]; w3 = wp[3 * D];
        }

        // fragments
        uint32_t ah[2][4], al[2][4], bh[4][2], bl[4][2];
        ldsm_x4(ah[0][0], ah[0][1], ah[0][2], ah[0][3], a_ld);
        ldsm_x4(ah[1][0], ah[1][1], ah[1][2], ah[1][3], a_ld + 768);
        ldsm_x4(al[0][0], al[0][1], al[0][2], al[0][3], a_ld + A_LO);
        ldsm_x4(al[1][0], al[1][1], al[1][2], al[1][3], a_ld + A_LO + 768);
        ldsm_x4(bh[0][0], bh[0][1], bh[1][0], bh[1][1], b_ld);
        ldsm_x4(bh[2][0], bh[2][1], bh[3][0], bh[3][1], b_ld + 768);
        ldsm_x4(bl[0][0], bl[0][1], bl[1][0], bl[1][1], b_ld + B_LO);
        ldsm_x4(bl[2][0], bl[2][1], bl[3][0], bl[3][1], b_ld + B_LO + 768);

        #pragma unroll
        for (int mt = 0; mt < 2; mt++)
            #pragma unroll
            for (int nt = 0; nt < 4; nt++) {
                mma_f16(acc[mt][nt], ah[mt], bh[nt]);
                mma_f16(acc[mt][nt], ah[mt], bl[nt]);
                mma_f16(acc[mt][nt], al[mt], bh[nt]);
            }
        __syncthreads();
    }

    // epilogue: scale rows by dis, store fp16
    #pragma unroll
    for (int mt = 0; mt < 2; mt++) {
        int r0 = block_row + wm * 32 + mt * 16 + g;
        int r1 = r0 + 8;
        float d0 = (r0 < M) ? g_dis[r0] : 0.f;
        float d1 = (r1 < M) ? g_dis[r1] : 0.f;
        #pragma unroll
        for (int nt = 0; nt < 4; nt++) {
            int col = n0 + wn * 32 + nt * 8 + 2 * t;
            float4 c = acc[mt][nt];
            if (r0 < M)
                *(__half2*)(OUT + (size_t)r0 * D + col) = __floats2half2_rn(c.x * d0, c.y * d0);
            if (r1 < M)
                *(__half2*)(OUT + (size_t)r1 * D + col) = __floats2half2_rn(c.z * d1, c.w * d1);
        }
    }
}

// ---------------- aggregation (warp per node), F=128, fp16 gathers --------
template <bool FUSE_GEMV>
__global__ __launch_bounds__(256)
void agg128_kernel(const __half* __restrict__ HW, const float* __restrict__ bias,
                   float* __restrict__ OUT, const float* __restrict__ W3) {
    int warp = (blockIdx.x * blockDim.x + threadIdx.x) >> 5;
    int lane = threadIdx.x & 31;
    if (warp >= N_NODES) return;
    int node = warp;

    const uint2* rowp = (const uint2*)(HW + (size_t)node * D) + lane;
    uint2 sv = *rowp;
    float2 a0 = __half22float2(*(const __half2*)&sv.x);
    float2 a1 = __half22float2(*(const __half2*)&sv.y);
    float4 acc = make_float4(a0.x, a0.y, a1.x, a1.y);

    int beg = g_base[node];
    int end = beg + g_counts[node];
    int e = beg;
    for (; e + 2 <= end; e += 2) {
        int s0 = __ldg(&g_csr_src[e]);
        int s1 = __ldg(&g_csr_src[e + 1]);
        uint2 v0 = *((const uint2*)(HW + (size_t)s0 * D) + lane);
        uint2 v1 = *((const uint2*)(HW + (size_t)s1 * D) + lane);
        float2 f00 = __half22float2(*(const __half2*)&v0.x);
        float2 f01 = __half22float2(*(const __half2*)&v0.y);
        float2 f10 = __half22float2(*(const __half2*)&v1.x);
        float2 f11 = __half22float2(*(const __half2*)&v1.y);
        acc.x += f00.x + f10.x; acc.y += f00.y + f10.y;
        acc.z += f01.x + f11.x; acc.w += f01.y + f11.y;
    }
    if (e < end) {
        int s = __ldg(&g_csr_src[e]);
        uint2 v = *((const uint2*)(HW + (size_t)s * D) + lane);
        float2 f0 = __half22float2(*(const __half2*)&v.x);
        float2 f1 = __half22float2(*(const __half2*)&v.y);
        acc.x += f0.x; acc.y += f0.y; acc.z += f1.x; acc.w += f1.y;
    }

    float dn = g_dis[node];
    float4 b = ((const float4*)bias)[lane];
    acc.x = fmaxf(acc.x * dn + b.x, 0.f);
    acc.y = fmaxf(acc.y * dn + b.y, 0.f);
    acc.z = fmaxf(acc.z * dn + b.z, 0.f);
    acc.w = fmaxf(acc.w * dn + b.w, 0.f);

    if (FUSE_GEMV) {
        float4 w = ((const float4*)W3)[lane];
        float dot = acc.x * w.x + acc.y * w.y + acc.z * w.z + acc.w * w.w;
        #pragma unroll
        for (int off = 16; off > 0; off >>= 1)
            dot += __shfl_down_sync(0xFFFFFFFFu, dot, off);
        if (lane == 0) g_hw3[node] = dot * dn;
    } else {
        ((float4*)(OUT + (size_t)node * D))[lane] = acc;
    }
}

// ---------------- layer 3: scalar aggregation -----------------------------
__global__ void agg3_kernel(const float* __restrict__ b3, float* __restrict__ OUT) {
    int node = blockIdx.x * blockDim.x + threadIdx.x;
    if (node >= N_NODES) return;
    float acc = g_hw3[node];
    int beg = g_base[node];
    int end = beg + g_counts[node];
    for (int e = beg; e < end; e++)
        acc += g_hw3[__ldg(&g_csr_src[e])];
    OUT[node] = fmaxf(acc * g_dis[node] + b3[0], 0.f);
}

// ---------------- launch ---------------------------------------------------
extern "C" void kernel_launch(void* const* d_in, const int* in_sizes, int n_in,
                              void* d_out, int out_size) {
    const float* x  = (const float*)d_in[0];
    const int*   ei = (const int*)d_in[1];
    const float* W1 = (const float*)d_in[2];
    const float* b1 = (const float*)d_in[3];
    const float* W2 = (const float*)d_in[4];
    const float* b2 = (const float*)d_in[5];
    const float* W3 = (const float*)d_in[6];
    const float* b3 = (const float*)d_in[7];
    float* out = (float*)d_out;

    const int* src = ei;
    const int* dst = ei + N_EDGES;

    __half* hw;  cudaGetSymbolAddress((void**)&hw,  g_hw);
    float*  act; cudaGetSymbolAddress((void**)&act, g_act);
    int* counts; cudaGetSymbolAddress((void**)&counts, g_counts);
    int* total;  cudaGetSymbolAddress((void**)&total,  g_total);

    int nb_nodes = (N_NODES + 255) / 256;
    int nb_edge4 = (N_EDGES / 4 + 255) / 256;
    int nb_warp  = (N_NODES * 32 + 255) / 256;
    dim3 gemm_grid((N_NODES + 127) / 128, 2);

    // preprocessing: unordered CSR by dst
    cudaMemsetAsync(counts, 0, N_NODES * sizeof(int));
    cudaMemsetAsync(total, 0, sizeof(int));
    hist_kernel<<<nb_edge4, 256>>>(dst);
    prefix_kernel<<<nb_nodes, 256>>>();
    scatter_kernel<<<nb_edge4, 256>>>(src, dst);

    // layer 1
    gemm_f16_kernel<<<gemm_grid, 256>>>(x, W1, hw, N_NODES);
    agg128_kernel<false><<<nb_warp, 256>>>(hw, b1, act, nullptr);
    // layer 2 (+ fused layer-3 GEMV)
    gemm_f16_kernel<<<gemm_grid, 256>>>(act, W2, hw, N_NODES);
    agg128_kernel<true><<<nb_warp, 256>>>(hw, b2, nullptr, W3);
    // layer 3 aggregation
    agg3_kernel<<<nb_nodes, 256>>>(b3, out);
}